// round 1
// baseline (speedup 1.0000x reference)
#include <cuda_runtime.h>
#include <cuda_bf16.h>
#include <math.h>

// ---------------- problem constants ----------------
#define NL   12
#define BB   4
#define TT   1024
#define CC   768
#define HH   12
#define HS   64
#define VV   50257
#define BT   (BB * TT)          // 4096
#define C3   (3 * CC)           // 2304
#define C4   (4 * CC)           // 3072
#define SCALE 0.125f            // 1/sqrt(64)

// ---------------- device scratch (static, no allocs) ----------------
__device__ float g_x[BT * CC];       // residual stream
__device__ float g_h[BT * CC];       // LN output
__device__ float g_qkv[BT * C3];     // qkv projection
__device__ float g_atty[BT * CC];    // attention output
__device__ float g_fc1[BT * C4];     // MLP hidden

// ---------------- embedding ----------------
__global__ void embed_kernel(const int* __restrict__ inp,
                             const float* __restrict__ wte,
                             const float* __restrict__ wpe,
                             float* __restrict__ x) {
    int i = blockIdx.x * blockDim.x + threadIdx.x;   // over BT*CC
    if (i >= BT * CC) return;
    int c  = i % CC;
    int bt = i / CC;
    int t  = bt % TT;
    int tok = inp[bt];
    x[i] = wte[(size_t)tok * CC + c] + wpe[(size_t)t * CC + c];
}

// ---------------- layernorm (one block per row) ----------------
__global__ void ln_kernel(const float* __restrict__ in,
                          const float* __restrict__ g,
                          const float* __restrict__ b,
                          float* __restrict__ out) {
    __shared__ float red[256];
    int row = blockIdx.x;
    int tid = threadIdx.x;
    const float* r = in + (size_t)row * CC;

    float s = 0.f;
    for (int c = tid; c < CC; c += 256) s += r[c];
    red[tid] = s; __syncthreads();
    for (int o = 128; o > 0; o >>= 1) { if (tid < o) red[tid] += red[tid + o]; __syncthreads(); }
    float mu = red[0] / CC;
    __syncthreads();

    float sq = 0.f;
    for (int c = tid; c < CC; c += 256) { float d = r[c] - mu; sq += d * d; }
    red[tid] = sq; __syncthreads();
    for (int o = 128; o > 0; o >>= 1) { if (tid < o) red[tid] += red[tid + o]; __syncthreads(); }
    float rstd = rsqrtf(red[0] / CC + 1e-5f);
    __syncthreads();

    float* w = out + (size_t)row * CC;
    for (int c = tid; c < CC; c += 256)
        w[c] = (r[c] - mu) * rstd * g[c] + b[c];
}

// ---------------- attention (one block per (b,h,q-row)) ----------------
__global__ void attn_kernel(const float* __restrict__ qkv,
                            float* __restrict__ out) {
    __shared__ float qs[HS];
    __shared__ float kv[64][HS + 1];   // padded to kill bank conflicts
    __shared__ float sc[TT];
    __shared__ float red[128];

    int bid  = blockIdx.x;
    int qrow = bid % TT;
    int bh   = bid / TT;
    int h    = bh % HH;
    int b    = bh / HH;
    int tid  = threadIdx.x;

    const float* base = qkv + (size_t)b * TT * C3 + (size_t)h * 3 * HS;

    for (int d = tid; d < HS; d += 128)
        qs[d] = base[(size_t)qrow * C3 + d];
    __syncthreads();

    int jmax = qrow;                   // causal: j <= qrow
    float lmax = -1e30f;
    for (int j0 = 0; j0 <= jmax; j0 += 64) {
        int jn = min(64, jmax + 1 - j0);
        for (int i = tid; i < jn * HS; i += 128) {
            int jj = i / HS, dd = i % HS;
            kv[jj][dd] = base[(size_t)(j0 + jj) * C3 + HS + dd];  // K
        }
        __syncthreads();
        if (tid < jn) {
            float acc = 0.f;
            #pragma unroll
            for (int d = 0; d < HS; d++) acc += qs[d] * kv[tid][d];
            acc *= SCALE;
            sc[j0 + tid] = acc;
            lmax = fmaxf(lmax, acc);
        }
        __syncthreads();
    }

    red[tid] = lmax; __syncthreads();
    for (int o = 64; o > 0; o >>= 1) { if (tid < o) red[tid] = fmaxf(red[tid], red[tid + o]); __syncthreads(); }
    float m = red[0];
    __syncthreads();

    float lsum = 0.f;
    for (int j = tid; j <= jmax; j += 128) {
        float e = __expf(sc[j] - m);
        sc[j] = e;
        lsum += e;
    }
    red[tid] = lsum; __syncthreads();
    for (int o = 64; o > 0; o >>= 1) { if (tid < o) red[tid] += red[tid + o]; __syncthreads(); }
    float inv = 1.0f / red[0];
    __syncthreads();

    // phase 2: out[d] = sum_j p[j] * V[j][d]
    int d    = tid % HS;
    int half = tid / HS;
    float acc = 0.f;
    for (int j0 = 0; j0 <= jmax; j0 += 64) {
        int jn = min(64, jmax + 1 - j0);
        for (int i = tid; i < jn * HS; i += 128) {
            int jj = i / HS, dd = i % HS;
            kv[jj][dd] = base[(size_t)(j0 + jj) * C3 + 2 * HS + dd];  // V
        }
        __syncthreads();
        for (int jj = half; jj < jn; jj += 2)
            acc += sc[j0 + jj] * kv[jj][d];
        __syncthreads();
    }
    red[tid] = acc; __syncthreads();
    if (tid < HS) {
        float r = (red[tid] + red[tid + HS]) * inv;
        out[((size_t)(b * TT + qrow)) * CC + h * HS + d] = r;
    }
}

// ---------------- tiled fp32 GEMM: C = A(MxK) @ B + epi ----------------
// TB=false: B is (K,N) row-major. TB=true: B is (N,K) row-major (NT).
template<bool TB, bool BIAS, bool GELU, bool RES>
__global__ void gemm_kernel(const float* __restrict__ A,
                            const float* __restrict__ Bm,
                            const float* __restrict__ bias,
                            const float* __restrict__ res,
                            float* __restrict__ Cm,
                            int M, int N, int K) {
    __shared__ float As[16][64];
    __shared__ float Bs[16][64 + 1];
    int tid = threadIdx.x;              // 256
    int tx = tid & 15, ty = tid >> 4;
    int row0 = blockIdx.y * 64, col0 = blockIdx.x * 64;
    float acc[4][4] = {};

    for (int k0 = 0; k0 < K; k0 += 16) {  // K is always a multiple of 16 here
        #pragma unroll
        for (int i = 0; i < 4; i++) {
            int idx = tid + i * 256;
            int r = idx >> 4, c = idx & 15;       // A tile 64 x 16
            float v = 0.f;
            if (row0 + r < M) v = A[(size_t)(row0 + r) * K + k0 + c];
            As[c][r] = v;
        }
        #pragma unroll
        for (int i = 0; i < 4; i++) {
            int idx = tid + i * 256;
            if (!TB) {
                int r = idx >> 6, c = idx & 63;   // B tile 16 x 64 (K x N)
                float v = 0.f;
                if (col0 + c < N) v = Bm[(size_t)(k0 + r) * N + col0 + c];
                Bs[r][c] = v;
            } else {
                int c = idx >> 4, r = idx & 15;   // iterate N rows, K contiguous
                float v = 0.f;
                if (col0 + c < N) v = Bm[(size_t)(col0 + c) * K + k0 + r];
                Bs[r][c] = v;
            }
        }
        __syncthreads();
        #pragma unroll
        for (int kk = 0; kk < 16; kk++) {
            float a[4], bb[4];
            #pragma unroll
            for (int i = 0; i < 4; i++) a[i] = As[kk][ty * 4 + i];
            #pragma unroll
            for (int j = 0; j < 4; j++) bb[j] = Bs[kk][tx * 4 + j];
            #pragma unroll
            for (int i = 0; i < 4; i++)
                #pragma unroll
                for (int j = 0; j < 4; j++)
                    acc[i][j] += a[i] * bb[j];
        }
        __syncthreads();
    }

    #pragma unroll
    for (int i = 0; i < 4; i++) {
        int r = row0 + ty * 4 + i;
        if (r >= M) continue;
        #pragma unroll
        for (int j = 0; j < 4; j++) {
            int c = col0 + tx * 4 + j;
            if (c >= N) continue;
            float v = acc[i][j];
            if (BIAS) v += bias[c];
            if (GELU) v = 0.5f * v * (1.0f + erff(v * 0.7071067811865475f));
            if (RES)  v += res[(size_t)r * N + c];
            Cm[(size_t)r * N + c] = v;
        }
    }
}

// ---------------- host orchestration ----------------
extern "C" void kernel_launch(void* const* d_in, const int* in_sizes, int n_in,
                              void* d_out, int out_size) {
    const int*   inp   = (const int*)  d_in[0];
    const float* wte   = (const float*)d_in[1];
    const float* wpe   = (const float*)d_in[2];
    const float* ln1_g = (const float*)d_in[3];
    const float* ln1_b = (const float*)d_in[4];
    const float* wqkv  = (const float*)d_in[5];
    const float* bqkv  = (const float*)d_in[6];
    const float* wout  = (const float*)d_in[7];
    const float* bout  = (const float*)d_in[8];
    const float* ln2_g = (const float*)d_in[9];
    const float* ln2_b = (const float*)d_in[10];
    const float* wfc1  = (const float*)d_in[11];
    const float* bfc1  = (const float*)d_in[12];
    const float* wfc2  = (const float*)d_in[13];
    const float* bfc2  = (const float*)d_in[14];
    const float* lnf_g = (const float*)d_in[15];
    const float* lnf_b = (const float*)d_in[16];
    float* logits = (float*)d_out;

    float *x, *h, *qkv, *atty, *fc1;
    cudaGetSymbolAddress((void**)&x,    g_x);
    cudaGetSymbolAddress((void**)&h,    g_h);
    cudaGetSymbolAddress((void**)&qkv,  g_qkv);
    cudaGetSymbolAddress((void**)&atty, g_atty);
    cudaGetSymbolAddress((void**)&fc1,  g_fc1);

    // embedding
    {
        int n = BT * CC;
        embed_kernel<<<(n + 255) / 256, 256>>>(inp, wte, wpe, x);
    }

    dim3 blk(256);
    for (int l = 0; l < NL; l++) {
        const float* g1 = ln1_g + (size_t)l * CC;
        const float* b1 = ln1_b + (size_t)l * CC;
        const float* wq = wqkv  + (size_t)l * CC * C3;
        const float* bq = bqkv  + (size_t)l * C3;
        const float* wo = wout  + (size_t)l * CC * CC;
        const float* bo = bout  + (size_t)l * CC;
        const float* g2 = ln2_g + (size_t)l * CC;
        const float* b2 = ln2_b + (size_t)l * CC;
        const float* w1 = wfc1  + (size_t)l * CC * C4;
        const float* bb1= bfc1  + (size_t)l * C4;
        const float* w2 = wfc2  + (size_t)l * C4 * CC;
        const float* bb2= bfc2  + (size_t)l * CC;

        // ln1
        ln_kernel<<<BT, 256>>>(x, g1, b1, h);
        // qkv = h @ wq + bq
        gemm_kernel<false, true, false, false>
            <<<dim3(C3 / 64, BT / 64), blk>>>(h, wq, bq, nullptr, qkv, BT, C3, CC);
        // attention
        attn_kernel<<<BB * HH * TT, 128>>>(qkv, atty);
        // x = x + atty @ wo + bo
        gemm_kernel<false, true, false, true>
            <<<dim3(CC / 64, BT / 64), blk>>>(atty, wo, bo, x, x, BT, CC, CC);
        // ln2
        ln_kernel<<<BT, 256>>>(x, g2, b2, h);
        // fc1 = gelu(h @ w1 + bb1)
        gemm_kernel<false, true, true, false>
            <<<dim3(C4 / 64, BT / 64), blk>>>(h, w1, bb1, nullptr, fc1, BT, C4, CC);
        // x = x + fc1 @ w2 + bb2
        gemm_kernel<false, true, false, true>
            <<<dim3(CC / 64, BT / 64), blk>>>(fc1, w2, bb2, x, x, BT, CC, C4);
    }

    // final LN
    ln_kernel<<<BT, 256>>>(x, lnf_g, lnf_b, h);
    // logits = h @ wte^T   (NT GEMM, no bias)
    gemm_kernel<true, false, false, false>
        <<<dim3((VV + 63) / 64, BT / 64), blk>>>(h, wte, nullptr, nullptr,
                                                 logits, BT, VV, CC);
}

// round 3
// speedup vs baseline: 1.9558x; 1.9558x over previous
#include <cuda_runtime.h>
#include <cuda_bf16.h>
#include <math.h>
#include <stdint.h>

// ---------------- problem constants ----------------
#define NL   12
#define BB   4
#define TT   1024
#define CC   768
#define HH   12
#define HS   64
#define VV   50257
#define BT   (BB * TT)          // 4096
#define C3   (3 * CC)           // 2304
#define C4   (4 * CC)           // 3072
#define SCALE 0.125f

// ---------------- device scratch (static, no allocs) ----------------
__device__ float g_x[BT * CC];
__device__ float g_h[BT * CC];
__device__ float g_qkv[BT * C3];
__device__ float g_atty[BT * CC];
__device__ float g_fc1[BT * C4];

__device__ __nv_bfloat16 g_ahi[BT * C4];
__device__ __nv_bfloat16 g_alo[BT * C4];
__device__ __nv_bfloat16 g_whi[C4 * CC];
__device__ __nv_bfloat16 g_wlo[C4 * CC];
__device__ __nv_bfloat16 g_tehi[(size_t)VV * CC];
__device__ __nv_bfloat16 g_telo[(size_t)VV * CC];

// ---------------- PTX helpers (all base sm_80-class, no 'a' features) ----
__device__ __forceinline__ uint32_t smem_u32(const void* p) {
    uint32_t a;
    asm("{ .reg .u64 t; cvta.to.shared.u64 t, %1; cvt.u32.u64 %0, t; }" : "=r"(a) : "l"(p));
    return a;
}
__device__ __forceinline__ void cp16(uint32_t dst, const void* src, int sz) {
    asm volatile("cp.async.ca.shared.global [%0], [%1], 16, %2;"
                 :: "r"(dst), "l"(src), "r"(sz) : "memory");
}
__device__ __forceinline__ void cp_commit() {
    asm volatile("cp.async.commit_group;" ::: "memory");
}
__device__ __forceinline__ void ldsm4(uint32_t* r, uint32_t a) {
    asm volatile("ldmatrix.sync.aligned.m8n8.x4.shared.b16 {%0,%1,%2,%3}, [%4];"
                 : "=r"(r[0]), "=r"(r[1]), "=r"(r[2]), "=r"(r[3]) : "r"(a));
}
__device__ __forceinline__ void mma16816(float* d, const uint32_t* a,
                                         uint32_t b0, uint32_t b1) {
    asm volatile(
        "mma.sync.aligned.m16n8k16.row.col.f32.bf16.bf16.f32 "
        "{%0,%1,%2,%3}, {%4,%5,%6,%7}, {%8,%9}, {%0,%1,%2,%3};"
        : "+f"(d[0]), "+f"(d[1]), "+f"(d[2]), "+f"(d[3])
        : "r"(a[0]), "r"(a[1]), "r"(a[2]), "r"(a[3]), "r"(b0), "r"(b1));
}

// ---------------- embedding ----------------
__global__ void embed_kernel(const int* __restrict__ inp,
                             const float* __restrict__ wte,
                             const float* __restrict__ wpe,
                             float* __restrict__ x) {
    int i = blockIdx.x * blockDim.x + threadIdx.x;
    if (i >= BT * CC) return;
    int c = i % CC;
    int bt = i / CC;
    int t = bt % TT;
    int tok = inp[bt];
    x[i] = wte[(size_t)tok * CC + c] + wpe[(size_t)t * CC + c];
}

// ---------------- layernorm ----------------
__global__ void ln_kernel(const float* __restrict__ in,
                          const float* __restrict__ g,
                          const float* __restrict__ b,
                          float* __restrict__ out) {
    __shared__ float red[256];
    int row = blockIdx.x;
    int tid = threadIdx.x;
    const float* r = in + (size_t)row * CC;

    float s = 0.f;
    for (int c = tid; c < CC; c += 256) s += r[c];
    red[tid] = s; __syncthreads();
    for (int o = 128; o > 0; o >>= 1) { if (tid < o) red[tid] += red[tid + o]; __syncthreads(); }
    float mu = red[0] / CC;
    __syncthreads();

    float sq = 0.f;
    for (int c = tid; c < CC; c += 256) { float d = r[c] - mu; sq += d * d; }
    red[tid] = sq; __syncthreads();
    for (int o = 128; o > 0; o >>= 1) { if (tid < o) red[tid] += red[tid + o]; __syncthreads(); }
    float rstd = rsqrtf(red[0] / CC + 1e-5f);
    __syncthreads();

    float* w = out + (size_t)row * CC;
    for (int c = tid; c < CC; c += 256)
        w[c] = (r[c] - mu) * rstd * g[c] + b[c];
}

// ---------------- attention (one block per (b,h,q-row)) ----------------
__global__ void attn_kernel(const float* __restrict__ qkv,
                            float* __restrict__ out) {
    __shared__ float qs[HS];
    __shared__ float kv[64][HS + 1];
    __shared__ float sc[TT];
    __shared__ float red[128];

    int bid = blockIdx.x;
    int qrow = bid % TT;
    int bh = bid / TT;
    int h = bh % HH;
    int b = bh / HH;
    int tid = threadIdx.x;

    const float* base = qkv + (size_t)b * TT * C3 + (size_t)h * 3 * HS;

    for (int d = tid; d < HS; d += 128)
        qs[d] = base[(size_t)qrow * C3 + d];
    __syncthreads();

    int jmax = qrow;
    float lmax = -1e30f;
    for (int j0 = 0; j0 <= jmax; j0 += 64) {
        int jn = min(64, jmax + 1 - j0);
        for (int i = tid; i < jn * HS; i += 128) {
            int jj = i / HS, dd = i % HS;
            kv[jj][dd] = base[(size_t)(j0 + jj) * C3 + HS + dd];
        }
        __syncthreads();
        if (tid < jn) {
            float acc = 0.f;
            #pragma unroll
            for (int d = 0; d < HS; d++) acc += qs[d] * kv[tid][d];
            acc *= SCALE;
            sc[j0 + tid] = acc;
            lmax = fmaxf(lmax, acc);
        }
        __syncthreads();
    }

    red[tid] = lmax; __syncthreads();
    for (int o = 64; o > 0; o >>= 1) { if (tid < o) red[tid] = fmaxf(red[tid], red[tid + o]); __syncthreads(); }
    float m = red[0];
    __syncthreads();

    float lsum = 0.f;
    for (int j = tid; j <= jmax; j += 128) {
        float e = __expf(sc[j] - m);
        sc[j] = e;
        lsum += e;
    }
    red[tid] = lsum; __syncthreads();
    for (int o = 64; o > 0; o >>= 1) { if (tid < o) red[tid] += red[tid + o]; __syncthreads(); }
    float inv = 1.0f / red[0];
    __syncthreads();

    int d = tid % HS;
    int half = tid / HS;
    float acc = 0.f;
    for (int j0 = 0; j0 <= jmax; j0 += 64) {
        int jn = min(64, jmax + 1 - j0);
        for (int i = tid; i < jn * HS; i += 128) {
            int jj = i / HS, dd = i % HS;
            kv[jj][dd] = base[(size_t)(j0 + jj) * C3 + 2 * HS + dd];
        }
        __syncthreads();
        for (int jj = half; jj < jn; jj += 2)
            acc += sc[j0 + jj] * kv[jj][d];
        __syncthreads();
    }
    red[tid] = acc; __syncthreads();
    if (tid < HS) {
        float r = (red[tid] + red[tid + HS]) * inv;
        out[((size_t)(b * TT + qrow)) * CC + h * HS + d] = r;
    }
}

// ---------------- hi/lo split: elementwise ----------------
__global__ void conv_hl_kernel(const float* __restrict__ x,
                               __nv_bfloat16* __restrict__ hi,
                               __nv_bfloat16* __restrict__ lo,
                               size_t n) {
    size_t i = (size_t)blockIdx.x * blockDim.x + threadIdx.x;
    if (i >= n) return;
    float v = x[i];
    __nv_bfloat16 h = __float2bfloat16(v);
    hi[i] = h;
    lo[i] = __float2bfloat16(v - __bfloat162float(h));
}

// ---------------- hi/lo split + transpose: W[K][N] -> out[N][K] ----------------
__global__ void conv_wt_kernel(const float* __restrict__ W,
                               __nv_bfloat16* __restrict__ hi,
                               __nv_bfloat16* __restrict__ lo,
                               int K, int N) {
    __shared__ float ts[32][33];
    int k0 = blockIdx.y * 32, n0 = blockIdx.x * 32;
    int tx = threadIdx.x, ty = threadIdx.y;   // 32 x 8
    #pragma unroll
    for (int i = 0; i < 32; i += 8)
        ts[ty + i][tx] = W[(size_t)(k0 + ty + i) * N + n0 + tx];
    __syncthreads();
    #pragma unroll
    for (int i = 0; i < 32; i += 8) {
        float v = ts[tx][ty + i];
        size_t o = (size_t)(n0 + ty + i) * K + k0 + tx;
        __nv_bfloat16 h = __float2bfloat16(v);
        hi[o] = h;
        lo[o] = __float2bfloat16(v - __bfloat162float(h));
    }
}

// ---------------- HMMA bf16x3 GEMM ----------------
// C[M][N] = (Ahi+Alo)[M][K] @ (Bhi+Blo)[N][K]^T  (3-term compensated)
// CTA tile 128x128, K-step 32, cp.async double buffer, mma.sync.m16n8k16.
#define TSTRIDE  80                  // bytes per smem row (64 used + 16 pad)
#define T_A_HI   0
#define T_A_LO   10240
#define T_B_HI   20480
#define T_B_LO   30720
#define T_STAGE  40960
#define GSMEM    (2 * T_STAGE)       // 81920 B

template<bool BIAS, bool GELU, bool RES>
__global__ void __launch_bounds__(256, 1)
gemm3_kernel(const __nv_bfloat16* __restrict__ Ahi, const __nv_bfloat16* __restrict__ Alo,
             const __nv_bfloat16* __restrict__ Bhi, const __nv_bfloat16* __restrict__ Blo,
             const float* __restrict__ bias, const float* __restrict__ res,
             float* __restrict__ C, int M, int N, int K) {
    extern __shared__ char smem[];
    uint32_t sb = smem_u32(smem);
    int tid = threadIdx.x;
    int lane = tid & 31, wid = tid >> 5;
    int wr = wid >> 1, wc = wid & 1;     // 4 x 2 warp grid
    int row0 = blockIdx.y * 128, col0 = blockIdx.x * 128;

    const char* pAhi = (const char*)Ahi;
    const char* pAlo = (const char*)Alo;
    const char* pBhi = (const char*)Bhi;
    const char* pBlo = (const char*)Blo;

    float acc[2][8][4];
    #pragma unroll
    for (int a = 0; a < 2; a++)
        #pragma unroll
        for (int b = 0; b < 8; b++)
            #pragma unroll
            for (int e = 0; e < 4; e++) acc[a][b][e] = 0.f;

    int nc = K / 32;
    size_t Kb = (size_t)K * 2;           // row stride in bytes

    // precompute per-thread load coords
    int l_row0 = tid >> 2;               // 0..63
    int l_p    = tid & 3;

    // --- tile loader: k-tile c into buffer c&1 ---
    auto load_tile = [&](int c) {
        uint32_t s = sb + (uint32_t)(c & 1) * T_STAGE;
        size_t kb = (size_t)c * 64;
        #pragma unroll
        for (int i = 0; i < 2; i++) {
            int row = l_row0 + i * 64;
            uint32_t so = (uint32_t)row * TSTRIDE + (uint32_t)l_p * 16;
            size_t ao = (size_t)(row0 + row) * Kb + kb + (size_t)l_p * 16;
            cp16(s + T_A_HI + so, pAhi + ao, 16);
            cp16(s + T_A_LO + so, pAlo + ao, 16);
            int nr = col0 + row;
            int v = (nr < N) ? 16 : 0;
            size_t bo = (size_t)((nr < N) ? nr : 0) * Kb + kb + (size_t)l_p * 16;
            cp16(s + T_B_HI + so, pBhi + bo, v);
            cp16(s + T_B_LO + so, pBlo + bo, v);
        }
        cp_commit();
    };

    load_tile(0);

    int lr = lane & 15;
    int lh = (lane >> 4) * 16;

    for (int c = 0; c < nc; c++) {
        if (c + 1 < nc) {
            load_tile(c + 1);
            asm volatile("cp.async.wait_group 1;" ::: "memory");
        } else {
            asm volatile("cp.async.wait_group 0;" ::: "memory");
        }
        __syncthreads();

        uint32_t s = sb + (uint32_t)(c & 1) * T_STAGE;
        #pragma unroll
        for (int ks = 0; ks < 2; ks++) {
            uint32_t ko = ks * 32;
            uint32_t ah[2][4], al[2][4];
            #pragma unroll
            for (int mt = 0; mt < 2; mt++) {
                uint32_t ad = s + T_A_HI +
                              (uint32_t)(wr * 32 + mt * 16 + lr) * TSTRIDE + ko + lh;
                ldsm4(ah[mt], ad);
                ldsm4(al[mt], ad + (T_A_LO - T_A_HI));
            }
            #pragma unroll
            for (int nt = 0; nt < 4; nt++) {
                uint32_t bd = s + T_B_HI +
                              (uint32_t)(wc * 64 + nt * 16 + lr) * TSTRIDE + ko + lh;
                uint32_t bh[4], bl[4];
                ldsm4(bh, bd);
                ldsm4(bl, bd + (T_B_LO - T_B_HI));
                #pragma unroll
                for (int mt = 0; mt < 2; mt++) {
                    #pragma unroll
                    for (int sub = 0; sub < 2; sub++) {
                        float* d = acc[mt][nt * 2 + sub];
                        mma16816(d, ah[mt], bh[sub], bh[sub + 2]);
                        mma16816(d, ah[mt], bl[sub], bl[sub + 2]);
                        mma16816(d, al[mt], bh[sub], bh[sub + 2]);
                    }
                }
            }
        }
        __syncthreads();
    }

    // ---- epilogue: fragment layout -> global ----
    int g = lane >> 2, tg = lane & 3;
    #pragma unroll
    for (int mt = 0; mt < 2; mt++) {
        int r0g = row0 + wr * 32 + mt * 16 + g;
        #pragma unroll
        for (int n8 = 0; n8 < 8; n8++) {
            int gc = col0 + wc * 64 + n8 * 8 + tg * 2;
            float* d = acc[mt][n8];
            #pragma unroll
            for (int e = 0; e < 4; e++) {
                int rr = r0g + ((e >= 2) ? 8 : 0);
                int cc_ = gc + (e & 1);
                if (cc_ < N) {
                    float v = d[e];
                    if (BIAS) v += bias[cc_];
                    if (GELU) v = 0.5f * v * (1.0f + erff(v * 0.7071067811865475f));
                    if (RES)  v += res[(size_t)rr * N + cc_];
                    C[(size_t)rr * N + cc_] = v;
                }
            }
        }
    }
}

// ---------------- host orchestration ----------------
static void conv_act(const float* x, __nv_bfloat16* hi, __nv_bfloat16* lo, size_t n) {
    conv_hl_kernel<<<(unsigned)((n + 255) / 256), 256>>>(x, hi, lo, n);
}
static void conv_wT(const float* W, __nv_bfloat16* hi, __nv_bfloat16* lo, int K, int N) {
    conv_wt_kernel<<<dim3(N / 32, K / 32), dim3(32, 8)>>>(W, hi, lo, K, N);
}

template<bool BIAS, bool GELU, bool RES>
static void gemm3(const __nv_bfloat16* ahi, const __nv_bfloat16* alo,
                  const __nv_bfloat16* bhi, const __nv_bfloat16* blo,
                  const float* bias, const float* res, float* C,
                  int M, int N, int K) {
    dim3 grid((N + 127) / 128, M / 128);
    gemm3_kernel<BIAS, GELU, RES><<<grid, 256, GSMEM>>>(
        ahi, alo, bhi, blo, bias, res, C, M, N, K);
}

extern "C" void kernel_launch(void* const* d_in, const int* in_sizes, int n_in,
                              void* d_out, int out_size) {
    const int*   inp   = (const int*)  d_in[0];
    const float* wte   = (const float*)d_in[1];
    const float* wpe   = (const float*)d_in[2];
    const float* ln1_g = (const float*)d_in[3];
    const float* ln1_b = (const float*)d_in[4];
    const float* wqkv  = (const float*)d_in[5];
    const float* bqkv  = (const float*)d_in[6];
    const float* wout  = (const float*)d_in[7];
    const float* bout  = (const float*)d_in[8];
    const float* ln2_g = (const float*)d_in[9];
    const float* ln2_b = (const float*)d_in[10];
    const float* wfc1  = (const float*)d_in[11];
    const float* bfc1  = (const float*)d_in[12];
    const float* wfc2  = (const float*)d_in[13];
    const float* bfc2  = (const float*)d_in[14];
    const float* lnf_g = (const float*)d_in[15];
    const float* lnf_b = (const float*)d_in[16];
    float* logits = (float*)d_out;

    float *x, *h, *qkv, *atty, *fc1;
    __nv_bfloat16 *ahi, *alo, *whi, *wlo, *tehi, *telo;
    cudaGetSymbolAddress((void**)&x,    g_x);
    cudaGetSymbolAddress((void**)&h,    g_h);
    cudaGetSymbolAddress((void**)&qkv,  g_qkv);
    cudaGetSymbolAddress((void**)&atty, g_atty);
    cudaGetSymbolAddress((void**)&fc1,  g_fc1);
    cudaGetSymbolAddress((void**)&ahi,  g_ahi);
    cudaGetSymbolAddress((void**)&alo,  g_alo);
    cudaGetSymbolAddress((void**)&whi,  g_whi);
    cudaGetSymbolAddress((void**)&wlo,  g_wlo);
    cudaGetSymbolAddress((void**)&tehi, g_tehi);
    cudaGetSymbolAddress((void**)&telo, g_telo);

    cudaFuncSetAttribute(gemm3_kernel<true,  false, false>, cudaFuncAttributeMaxDynamicSharedMemorySize, GSMEM);
    cudaFuncSetAttribute(gemm3_kernel<true,  false, true >, cudaFuncAttributeMaxDynamicSharedMemorySize, GSMEM);
    cudaFuncSetAttribute(gemm3_kernel<true,  true,  false>, cudaFuncAttributeMaxDynamicSharedMemorySize, GSMEM);
    cudaFuncSetAttribute(gemm3_kernel<false, false, false>, cudaFuncAttributeMaxDynamicSharedMemorySize, GSMEM);

    embed_kernel<<<(BT * CC + 255) / 256, 256>>>(inp, wte, wpe, x);

    for (int l = 0; l < NL; l++) {
        const float* g1  = ln1_g + (size_t)l * CC;
        const float* b1  = ln1_b + (size_t)l * CC;
        const float* wq  = wqkv  + (size_t)l * CC * C3;
        const float* bq  = bqkv  + (size_t)l * C3;
        const float* wo  = wout  + (size_t)l * CC * CC;
        const float* bo  = bout  + (size_t)l * CC;
        const float* g2  = ln2_g + (size_t)l * CC;
        const float* b2  = ln2_b + (size_t)l * CC;
        const float* w1  = wfc1  + (size_t)l * CC * C4;
        const float* bb1 = bfc1  + (size_t)l * C4;
        const float* w2  = wfc2  + (size_t)l * C4 * CC;
        const float* bb2 = bfc2  + (size_t)l * CC;

        // ln1 -> h ; qkv = h @ wq + bq
        ln_kernel<<<BT, 256>>>(x, g1, b1, h);
        conv_act(h, ahi, alo, (size_t)BT * CC);
        conv_wT(wq, whi, wlo, CC, C3);
        gemm3<true, false, false>(ahi, alo, whi, wlo, bq, nullptr, qkv, BT, C3, CC);

        // attention
        attn_kernel<<<BB * HH * TT, 128>>>(qkv, atty);

        // x = x + atty @ wo + bo
        conv_act(atty, ahi, alo, (size_t)BT * CC);
        conv_wT(wo, whi, wlo, CC, CC);
        gemm3<true, false, true>(ahi, alo, whi, wlo, bo, x, x, BT, CC, CC);

        // ln2 -> h ; fc1 = gelu(h @ w1 + bb1)
        ln_kernel<<<BT, 256>>>(x, g2, b2, h);
        conv_act(h, ahi, alo, (size_t)BT * CC);
        conv_wT(w1, whi, wlo, CC, C4);
        gemm3<true, true, false>(ahi, alo, whi, wlo, bb1, nullptr, fc1, BT, C4, CC);

        // x = x + fc1 @ w2 + bb2
        conv_act(fc1, ahi, alo, (size_t)BT * C4);
        conv_wT(w2, whi, wlo, C4, CC);
        gemm3<true, false, true>(ahi, alo, whi, wlo, bb2, x, x, BT, CC, C4);
    }

    // final LN + weight-tied head
    ln_kernel<<<BT, 256>>>(x, lnf_g, lnf_b, h);
    conv_act(h, ahi, alo, (size_t)BT * CC);
    conv_act(wte, tehi, telo, (size_t)VV * CC);   // wte already [N][K]
    gemm3<false, false, false>(ahi, alo, tehi, telo, nullptr, nullptr,
                               logits, BT, VV, CC);
}

// round 4
// speedup vs baseline: 2.1469x; 1.0977x over previous
#include <cuda_runtime.h>
#include <cuda_bf16.h>
#include <cuda_fp16.h>
#include <math.h>
#include <stdint.h>

// ---------------- problem constants ----------------
#define NL   12
#define BB   4
#define TT   1024
#define CC   768
#define HH   12
#define HS   64
#define VV   50257
#define BT   (BB * TT)          // 4096
#define C3   (3 * CC)           // 2304
#define C4   (4 * CC)           // 3072
#define SCALE 0.125f

// ---------------- device scratch (static, no allocs) ----------------
__device__ float g_x[BT * CC];            // residual stream
__device__ float g_qkv[BT * C3];          // qkv projection (fp32 for attn)
__device__ __nv_bfloat16 g_ahi[BT * CC];  // activation hi (LN out / attn out)
__device__ __nv_bfloat16 g_alo[BT * CC];
__device__ __nv_bfloat16 g_fhi[BT * C4];  // fc1 hidden hi/lo
__device__ __nv_bfloat16 g_flo[BT * C4];
__device__ __nv_bfloat16 g_whi[C4 * CC];  // transposed weight hi/lo
__device__ __nv_bfloat16 g_wlo[C4 * CC];
__device__ __half g_ahf[BT * CC];         // final LN out, fp16
__device__ __half g_tef[(size_t)VV * CC]; // wte fp16 (already [N][K])

// ---------------- PTX helpers (base sm_80-class only) ----------------
__device__ __forceinline__ uint32_t smem_u32(const void* p) {
    uint32_t a;
    asm("{ .reg .u64 t; cvta.to.shared.u64 t, %1; cvt.u32.u64 %0, t; }" : "=r"(a) : "l"(p));
    return a;
}
__device__ __forceinline__ void cp16(uint32_t dst, const void* src, int sz) {
    asm volatile("cp.async.ca.shared.global [%0], [%1], 16, %2;"
                 :: "r"(dst), "l"(src), "r"(sz) : "memory");
}
__device__ __forceinline__ void cp_commit() {
    asm volatile("cp.async.commit_group;" ::: "memory");
}
__device__ __forceinline__ void ldsm4(uint32_t* r, uint32_t a) {
    asm volatile("ldmatrix.sync.aligned.m8n8.x4.shared.b16 {%0,%1,%2,%3}, [%4];"
                 : "=r"(r[0]), "=r"(r[1]), "=r"(r[2]), "=r"(r[3]) : "r"(a));
}
__device__ __forceinline__ void mma_bf16(float* d, const uint32_t* a,
                                         uint32_t b0, uint32_t b1) {
    asm volatile(
        "mma.sync.aligned.m16n8k16.row.col.f32.bf16.bf16.f32 "
        "{%0,%1,%2,%3}, {%4,%5,%6,%7}, {%8,%9}, {%0,%1,%2,%3};"
        : "+f"(d[0]), "+f"(d[1]), "+f"(d[2]), "+f"(d[3])
        : "r"(a[0]), "r"(a[1]), "r"(a[2]), "r"(a[3]), "r"(b0), "r"(b1));
}
__device__ __forceinline__ void mma_fp16(float* d, const uint32_t* a,
                                         uint32_t b0, uint32_t b1) {
    asm volatile(
        "mma.sync.aligned.m16n8k16.row.col.f32.f16.f16.f32 "
        "{%0,%1,%2,%3}, {%4,%5,%6,%7}, {%8,%9}, {%0,%1,%2,%3};"
        : "+f"(d[0]), "+f"(d[1]), "+f"(d[2]), "+f"(d[3])
        : "r"(a[0]), "r"(a[1]), "r"(a[2]), "r"(a[3]), "r"(b0), "r"(b1));
}

// ---------------- embedding ----------------
__global__ void embed_kernel(const int* __restrict__ inp,
                             const float* __restrict__ wte,
                             const float* __restrict__ wpe,
                             float* __restrict__ x) {
    int i = blockIdx.x * blockDim.x + threadIdx.x;
    if (i >= BT * CC) return;
    int c = i % CC;
    int bt = i / CC;
    int t = bt % TT;
    int tok = inp[bt];
    x[i] = wte[(size_t)tok * CC + c] + wpe[(size_t)t * CC + c];
}

// ---------------- layernorm -> bf16 hi/lo ----------------
__global__ void ln_hl_kernel(const float* __restrict__ in,
                             const float* __restrict__ g,
                             const float* __restrict__ b,
                             __nv_bfloat16* __restrict__ hi,
                             __nv_bfloat16* __restrict__ lo) {
    __shared__ float red[256];
    int row = blockIdx.x;
    int tid = threadIdx.x;
    const float* r = in + (size_t)row * CC;

    float s = 0.f;
    for (int c = tid; c < CC; c += 256) s += r[c];
    red[tid] = s; __syncthreads();
    for (int o = 128; o > 0; o >>= 1) { if (tid < o) red[tid] += red[tid + o]; __syncthreads(); }
    float mu = red[0] / CC;
    __syncthreads();

    float sq = 0.f;
    for (int c = tid; c < CC; c += 256) { float d = r[c] - mu; sq += d * d; }
    red[tid] = sq; __syncthreads();
    for (int o = 128; o > 0; o >>= 1) { if (tid < o) red[tid] += red[tid + o]; __syncthreads(); }
    float rstd = rsqrtf(red[0] / CC + 1e-5f);
    __syncthreads();

    size_t base = (size_t)row * CC;
    for (int c = tid; c < CC; c += 256) {
        float v = (r[c] - mu) * rstd * g[c] + b[c];
        __nv_bfloat16 h = __float2bfloat16(v);
        hi[base + c] = h;
        lo[base + c] = __float2bfloat16(v - __bfloat162float(h));
    }
}

// ---------------- final layernorm -> fp16 ----------------
__global__ void ln_hf_kernel(const float* __restrict__ in,
                             const float* __restrict__ g,
                             const float* __restrict__ b,
                             __half* __restrict__ out) {
    __shared__ float red[256];
    int row = blockIdx.x;
    int tid = threadIdx.x;
    const float* r = in + (size_t)row * CC;

    float s = 0.f;
    for (int c = tid; c < CC; c += 256) s += r[c];
    red[tid] = s; __syncthreads();
    for (int o = 128; o > 0; o >>= 1) { if (tid < o) red[tid] += red[tid + o]; __syncthreads(); }
    float mu = red[0] / CC;
    __syncthreads();

    float sq = 0.f;
    for (int c = tid; c < CC; c += 256) { float d = r[c] - mu; sq += d * d; }
    red[tid] = sq; __syncthreads();
    for (int o = 128; o > 0; o >>= 1) { if (tid < o) red[tid] += red[tid + o]; __syncthreads(); }
    float rstd = rsqrtf(red[0] / CC + 1e-5f);
    __syncthreads();

    size_t base = (size_t)row * CC;
    for (int c = tid; c < CC; c += 256)
        out[base + c] = __float2half((r[c] - mu) * rstd * g[c] + b[c]);
}

// ---------------- attention -> bf16 hi/lo output ----------------
__global__ void attn_kernel(const float* __restrict__ qkv,
                            __nv_bfloat16* __restrict__ ohi,
                            __nv_bfloat16* __restrict__ olo) {
    __shared__ float qs[HS];
    __shared__ float kv[64][HS + 1];
    __shared__ float sc[TT];
    __shared__ float red[128];

    int bid = blockIdx.x;
    int qrow = bid % TT;
    int bh = bid / TT;
    int h = bh % HH;
    int b = bh / HH;
    int tid = threadIdx.x;

    const float* base = qkv + (size_t)b * TT * C3 + (size_t)h * 3 * HS;

    for (int d = tid; d < HS; d += 128)
        qs[d] = base[(size_t)qrow * C3 + d];
    __syncthreads();

    int jmax = qrow;
    float lmax = -1e30f;
    for (int j0 = 0; j0 <= jmax; j0 += 64) {
        int jn = min(64, jmax + 1 - j0);
        for (int i = tid; i < jn * HS; i += 128) {
            int jj = i / HS, dd = i % HS;
            kv[jj][dd] = base[(size_t)(j0 + jj) * C3 + HS + dd];
        }
        __syncthreads();
        if (tid < jn) {
            float acc = 0.f;
            #pragma unroll
            for (int d = 0; d < HS; d++) acc += qs[d] * kv[tid][d];
            acc *= SCALE;
            sc[j0 + tid] = acc;
            lmax = fmaxf(lmax, acc);
        }
        __syncthreads();
    }

    red[tid] = lmax; __syncthreads();
    for (int o = 64; o > 0; o >>= 1) { if (tid < o) red[tid] = fmaxf(red[tid], red[tid + o]); __syncthreads(); }
    float m = red[0];
    __syncthreads();

    float lsum = 0.f;
    for (int j = tid; j <= jmax; j += 128) {
        float e = __expf(sc[j] - m);
        sc[j] = e;
        lsum += e;
    }
    red[tid] = lsum; __syncthreads();
    for (int o = 64; o > 0; o >>= 1) { if (tid < o) red[tid] += red[tid + o]; __syncthreads(); }
    float inv = 1.0f / red[0];
    __syncthreads();

    int d = tid % HS;
    int half = tid / HS;
    float acc = 0.f;
    for (int j0 = 0; j0 <= jmax; j0 += 64) {
        int jn = min(64, jmax + 1 - j0);
        for (int i = tid; i < jn * HS; i += 128) {
            int jj = i / HS, dd = i % HS;
            kv[jj][dd] = base[(size_t)(j0 + jj) * C3 + 2 * HS + dd];
        }
        __syncthreads();
        for (int jj = half; jj < jn; jj += 2)
            acc += sc[j0 + jj] * kv[jj][d];
        __syncthreads();
    }
    red[tid] = acc; __syncthreads();
    if (tid < HS) {
        float r = (red[tid] + red[tid + HS]) * inv;
        size_t idx = ((size_t)(b * TT + qrow)) * CC + h * HS + d;
        __nv_bfloat16 hv = __float2bfloat16(r);
        ohi[idx] = hv;
        olo[idx] = __float2bfloat16(r - __bfloat162float(hv));
    }
}

// ---------------- weight transpose + hi/lo split: W[K][N] -> [N][K] ----------------
__global__ void conv_wt_kernel(const float* __restrict__ W,
                               __nv_bfloat16* __restrict__ hi,
                               __nv_bfloat16* __restrict__ lo,
                               int K, int N) {
    __shared__ float ts[32][33];
    int k0 = blockIdx.y * 32, n0 = blockIdx.x * 32;
    int tx = threadIdx.x, ty = threadIdx.y;   // 32 x 8
    #pragma unroll
    for (int i = 0; i < 32; i += 8)
        ts[ty + i][tx] = W[(size_t)(k0 + ty + i) * N + n0 + tx];
    __syncthreads();
    #pragma unroll
    for (int i = 0; i < 32; i += 8) {
        float v = ts[tx][ty + i];
        size_t o = (size_t)(n0 + ty + i) * K + k0 + tx;
        __nv_bfloat16 h = __float2bfloat16(v);
        hi[o] = h;
        lo[o] = __float2bfloat16(v - __bfloat162float(h));
    }
}

// ---------------- wte -> fp16 ----------------
__global__ void conv_hf_kernel(const float* __restrict__ x,
                               __half* __restrict__ out, size_t n) {
    size_t i = (size_t)blockIdx.x * blockDim.x + threadIdx.x;
    if (i < n) out[i] = __float2half(x[i]);
}

// ---------------- HMMA bf16x3 GEMM (internal layers) ----------------
#define TSTRIDE  80
#define T_A_HI   0
#define T_A_LO   10240
#define T_B_HI   20480
#define T_B_LO   30720
#define T_STAGE  40960
#define GSMEM    (2 * T_STAGE)

template<bool BIAS, bool GELU, bool RES, bool OUTHL>
__global__ void __launch_bounds__(256, 1)
gemm3_kernel(const __nv_bfloat16* __restrict__ Ahi, const __nv_bfloat16* __restrict__ Alo,
             const __nv_bfloat16* __restrict__ Bhi, const __nv_bfloat16* __restrict__ Blo,
             const float* __restrict__ bias, const float* __restrict__ res,
             float* __restrict__ C,
             __nv_bfloat16* __restrict__ Chi, __nv_bfloat16* __restrict__ Clo,
             int M, int N, int K) {
    extern __shared__ char smem[];
    uint32_t sb = smem_u32(smem);
    int tid = threadIdx.x;
    int lane = tid & 31, wid = tid >> 5;
    int wr = wid >> 1, wc = wid & 1;     // 4 x 2 warp grid
    int row0 = blockIdx.y * 128, col0 = blockIdx.x * 128;

    const char* pAhi = (const char*)Ahi;
    const char* pAlo = (const char*)Alo;
    const char* pBhi = (const char*)Bhi;
    const char* pBlo = (const char*)Blo;

    float acc[2][8][4];
    #pragma unroll
    for (int a = 0; a < 2; a++)
        #pragma unroll
        for (int b = 0; b < 8; b++)
            #pragma unroll
            for (int e = 0; e < 4; e++) acc[a][b][e] = 0.f;

    int nc = K / 32;
    size_t Kb = (size_t)K * 2;

    int l_row0 = tid >> 2;
    int l_p    = tid & 3;

    auto load_tile = [&](int c) {
        uint32_t s = sb + (uint32_t)(c & 1) * T_STAGE;
        size_t kb = (size_t)c * 64;
        #pragma unroll
        for (int i = 0; i < 2; i++) {
            int row = l_row0 + i * 64;
            uint32_t so = (uint32_t)row * TSTRIDE + (uint32_t)l_p * 16;
            size_t ao = (size_t)(row0 + row) * Kb + kb + (size_t)l_p * 16;
            cp16(s + T_A_HI + so, pAhi + ao, 16);
            cp16(s + T_A_LO + so, pAlo + ao, 16);
            int nr = col0 + row;
            int v = (nr < N) ? 16 : 0;
            size_t bo = (size_t)((nr < N) ? nr : 0) * Kb + kb + (size_t)l_p * 16;
            cp16(s + T_B_HI + so, pBhi + bo, v);
            cp16(s + T_B_LO + so, pBlo + bo, v);
        }
        cp_commit();
    };

    load_tile(0);

    int lr = lane & 15;
    int lh = (lane >> 4) * 16;

    for (int c = 0; c < nc; c++) {
        if (c + 1 < nc) {
            load_tile(c + 1);
            asm volatile("cp.async.wait_group 1;" ::: "memory");
        } else {
            asm volatile("cp.async.wait_group 0;" ::: "memory");
        }
        __syncthreads();

        uint32_t s = sb + (uint32_t)(c & 1) * T_STAGE;
        #pragma unroll
        for (int ks = 0; ks < 2; ks++) {
            uint32_t ko = ks * 32;
            uint32_t ah[2][4], al[2][4];
            #pragma unroll
            for (int mt = 0; mt < 2; mt++) {
                uint32_t ad = s + T_A_HI +
                              (uint32_t)(wr * 32 + mt * 16 + lr) * TSTRIDE + ko + lh;
                ldsm4(ah[mt], ad);
                ldsm4(al[mt], ad + (T_A_LO - T_A_HI));
            }
            #pragma unroll
            for (int nt = 0; nt < 4; nt++) {
                uint32_t bd = s + T_B_HI +
                              (uint32_t)(wc * 64 + nt * 16 + lr) * TSTRIDE + ko + lh;
                uint32_t bh[4], bl[4];
                ldsm4(bh, bd);
                ldsm4(bl, bd + (T_B_LO - T_B_HI));
                #pragma unroll
                for (int mt = 0; mt < 2; mt++) {
                    #pragma unroll
                    for (int sub = 0; sub < 2; sub++) {
                        float* d = acc[mt][nt * 2 + sub];
                        mma_bf16(d, ah[mt], bh[sub], bh[sub + 2]);
                        mma_bf16(d, ah[mt], bl[sub], bl[sub + 2]);
                        mma_bf16(d, al[mt], bh[sub], bh[sub + 2]);
                    }
                }
            }
        }
        __syncthreads();
    }

    int g = lane >> 2, tg = lane & 3;
    #pragma unroll
    for (int mt = 0; mt < 2; mt++) {
        int r0g = row0 + wr * 32 + mt * 16 + g;
        #pragma unroll
        for (int n8 = 0; n8 < 8; n8++) {
            int gc = col0 + wc * 64 + n8 * 8 + tg * 2;
            float* d = acc[mt][n8];
            #pragma unroll
            for (int e = 0; e < 4; e++) {
                int rr = r0g + ((e >= 2) ? 8 : 0);
                int cc_ = gc + (e & 1);
                if (cc_ < N) {
                    float v = d[e];
                    if (BIAS) v += bias[cc_];
                    if (GELU) v = 0.5f * v * (1.0f + erff(v * 0.7071067811865475f));
                    if (RES)  v += res[(size_t)rr * N + cc_];
                    size_t idx = (size_t)rr * N + cc_;
                    if (OUTHL) {
                        __nv_bfloat16 hv = __float2bfloat16(v);
                        Chi[idx] = hv;
                        Clo[idx] = __float2bfloat16(v - __bfloat162float(hv));
                    } else {
                        C[idx] = v;
                    }
                }
            }
        }
    }
}

// ---------------- HMMA plain fp16 GEMM (LM head) ----------------
#define H_A      0
#define H_B      10240
#define H_STAGE  20480
#define GSMEMH   (2 * H_STAGE)

__global__ void __launch_bounds__(256, 2)
gemmh_kernel(const __half* __restrict__ A, const __half* __restrict__ B,
             float* __restrict__ C, int M, int N, int K) {
    extern __shared__ char smem[];
    uint32_t sb = smem_u32(smem);
    int tid = threadIdx.x;
    int lane = tid & 31, wid = tid >> 5;
    int wr = wid >> 1, wc = wid & 1;
    int row0 = blockIdx.y * 128, col0 = blockIdx.x * 128;

    const char* pA = (const char*)A;
    const char* pB = (const char*)B;

    float acc[2][8][4];
    #pragma unroll
    for (int a = 0; a < 2; a++)
        #pragma unroll
        for (int b = 0; b < 8; b++)
            #pragma unroll
            for (int e = 0; e < 4; e++) acc[a][b][e] = 0.f;

    int nc = K / 32;
    size_t Kb = (size_t)K * 2;
    int l_row0 = tid >> 2;
    int l_p    = tid & 3;

    auto load_tile = [&](int c) {
        uint32_t s = sb + (uint32_t)(c & 1) * H_STAGE;
        size_t kb = (size_t)c * 64;
        #pragma unroll
        for (int i = 0; i < 2; i++) {
            int row = l_row0 + i * 64;
            uint32_t so = (uint32_t)row * TSTRIDE + (uint32_t)l_p * 16;
            size_t ao = (size_t)(row0 + row) * Kb + kb + (size_t)l_p * 16;
            cp16(s + H_A + so, pA + ao, 16);
            int nr = col0 + row;
            int v = (nr < N) ? 16 : 0;
            size_t bo = (size_t)((nr < N) ? nr : 0) * Kb + kb + (size_t)l_p * 16;
            cp16(s + H_B + so, pB + bo, v);
        }
        cp_commit();
    };

    load_tile(0);

    int lr = lane & 15;
    int lh = (lane >> 4) * 16;

    for (int c = 0; c < nc; c++) {
        if (c + 1 < nc) {
            load_tile(c + 1);
            asm volatile("cp.async.wait_group 1;" ::: "memory");
        } else {
            asm volatile("cp.async.wait_group 0;" ::: "memory");
        }
        __syncthreads();

        uint32_t s = sb + (uint32_t)(c & 1) * H_STAGE;
        #pragma unroll
        for (int ks = 0; ks < 2; ks++) {
            uint32_t ko = ks * 32;
            uint32_t ah[2][4];
            #pragma unroll
            for (int mt = 0; mt < 2; mt++) {
                uint32_t ad = s + H_A +
                              (uint32_t)(wr * 32 + mt * 16 + lr) * TSTRIDE + ko + lh;
                ldsm4(ah[mt], ad);
            }
            #pragma unroll
            for (int nt = 0; nt < 4; nt++) {
                uint32_t bd = s + H_B +
                              (uint32_t)(wc * 64 + nt * 16 + lr) * TSTRIDE + ko + lh;
                uint32_t bf[4];
                ldsm4(bf, bd);
                #pragma unroll
                for (int mt = 0; mt < 2; mt++) {
                    #pragma unroll
                    for (int sub = 0; sub < 2; sub++)
                        mma_fp16(acc[mt][nt * 2 + sub], ah[mt], bf[sub], bf[sub + 2]);
                }
            }
        }
        __syncthreads();
    }

    int g = lane >> 2, tg = lane & 3;
    #pragma unroll
    for (int mt = 0; mt < 2; mt++) {
        int r0g = row0 + wr * 32 + mt * 16 + g;
        #pragma unroll
        for (int n8 = 0; n8 < 8; n8++) {
            int gc = col0 + wc * 64 + n8 * 8 + tg * 2;
            float* d = acc[mt][n8];
            #pragma unroll
            for (int e = 0; e < 4; e++) {
                int rr = r0g + ((e >= 2) ? 8 : 0);
                int cc_ = gc + (e & 1);
                if (cc_ < N) C[(size_t)rr * N + cc_] = d[e];
            }
        }
    }
}

// ---------------- host orchestration ----------------
static void conv_wT(const float* W, __nv_bfloat16* hi, __nv_bfloat16* lo, int K, int N) {
    conv_wt_kernel<<<dim3(N / 32, K / 32), dim3(32, 8)>>>(W, hi, lo, K, N);
}

template<bool BIAS, bool GELU, bool RES, bool OUTHL>
static void gemm3(const __nv_bfloat16* ahi, const __nv_bfloat16* alo,
                  const __nv_bfloat16* bhi, const __nv_bfloat16* blo,
                  const float* bias, const float* res,
                  float* C, __nv_bfloat16* Chi, __nv_bfloat16* Clo,
                  int M, int N, int K) {
    dim3 grid((N + 127) / 128, M / 128);
    gemm3_kernel<BIAS, GELU, RES, OUTHL><<<grid, 256, GSMEM>>>(
        ahi, alo, bhi, blo, bias, res, C, Chi, Clo, M, N, K);
}

extern "C" void kernel_launch(void* const* d_in, const int* in_sizes, int n_in,
                              void* d_out, int out_size) {
    const int*   inp   = (const int*)  d_in[0];
    const float* wte   = (const float*)d_in[1];
    const float* wpe   = (const float*)d_in[2];
    const float* ln1_g = (const float*)d_in[3];
    const float* ln1_b = (const float*)d_in[4];
    const float* wqkv  = (const float*)d_in[5];
    const float* bqkv  = (const float*)d_in[6];
    const float* wout  = (const float*)d_in[7];
    const float* bout  = (const float*)d_in[8];
    const float* ln2_g = (const float*)d_in[9];
    const float* ln2_b = (const float*)d_in[10];
    const float* wfc1  = (const float*)d_in[11];
    const float* bfc1  = (const float*)d_in[12];
    const float* wfc2  = (const float*)d_in[13];
    const float* bfc2  = (const float*)d_in[14];
    const float* lnf_g = (const float*)d_in[15];
    const float* lnf_b = (const float*)d_in[16];
    float* logits = (float*)d_out;

    float *x, *qkv;
    __nv_bfloat16 *ahi, *alo, *fhi, *flo, *whi, *wlo;
    __half *ahf, *tef;
    cudaGetSymbolAddress((void**)&x,   g_x);
    cudaGetSymbolAddress((void**)&qkv, g_qkv);
    cudaGetSymbolAddress((void**)&ahi, g_ahi);
    cudaGetSymbolAddress((void**)&alo, g_alo);
    cudaGetSymbolAddress((void**)&fhi, g_fhi);
    cudaGetSymbolAddress((void**)&flo, g_flo);
    cudaGetSymbolAddress((void**)&whi, g_whi);
    cudaGetSymbolAddress((void**)&wlo, g_wlo);
    cudaGetSymbolAddress((void**)&ahf, g_ahf);
    cudaGetSymbolAddress((void**)&tef, g_tef);

    cudaFuncSetAttribute(gemm3_kernel<true,  false, false, false>, cudaFuncAttributeMaxDynamicSharedMemorySize, GSMEM);
    cudaFuncSetAttribute(gemm3_kernel<true,  false, true,  false>, cudaFuncAttributeMaxDynamicSharedMemorySize, GSMEM);
    cudaFuncSetAttribute(gemm3_kernel<true,  true,  false, true >, cudaFuncAttributeMaxDynamicSharedMemorySize, GSMEM);
    cudaFuncSetAttribute(gemmh_kernel, cudaFuncAttributeMaxDynamicSharedMemorySize, GSMEMH);

    embed_kernel<<<(BT * CC + 255) / 256, 256>>>(inp, wte, wpe, x);

    for (int l = 0; l < NL; l++) {
        const float* g1  = ln1_g + (size_t)l * CC;
        const float* b1  = ln1_b + (size_t)l * CC;
        const float* wq  = wqkv  + (size_t)l * CC * C3;
        const float* bq  = bqkv  + (size_t)l * C3;
        const float* wo  = wout  + (size_t)l * CC * CC;
        const float* bo  = bout  + (size_t)l * CC;
        const float* g2  = ln2_g + (size_t)l * CC;
        const float* b2  = ln2_b + (size_t)l * CC;
        const float* w1  = wfc1  + (size_t)l * CC * C4;
        const float* bb1 = bfc1  + (size_t)l * C4;
        const float* w2  = wfc2  + (size_t)l * C4 * CC;
        const float* bb2 = bfc2  + (size_t)l * CC;

        // ln1 -> hi/lo ; qkv = h @ wq + bq (fp32 out for attn)
        ln_hl_kernel<<<BT, 256>>>(x, g1, b1, ahi, alo);
        conv_wT(wq, whi, wlo, CC, C3);
        gemm3<true, false, false, false>(ahi, alo, whi, wlo, bq, nullptr,
                                         qkv, nullptr, nullptr, BT, C3, CC);

        // attention -> hi/lo
        attn_kernel<<<BB * HH * TT, 128>>>(qkv, ahi, alo);

        // x = x + atty @ wo + bo
        conv_wT(wo, whi, wlo, CC, CC);
        gemm3<true, false, true, false>(ahi, alo, whi, wlo, bo, x,
                                        x, nullptr, nullptr, BT, CC, CC);

        // ln2 -> hi/lo ; fc1 = gelu(h @ w1 + bb1) -> hi/lo directly
        ln_hl_kernel<<<BT, 256>>>(x, g2, b2, ahi, alo);
        conv_wT(w1, whi, wlo, CC, C4);
        gemm3<true, true, false, true>(ahi, alo, whi, wlo, bb1, nullptr,
                                       nullptr, fhi, flo, BT, C4, CC);

        // x = x + fc1 @ w2 + bb2
        conv_wT(w2, whi, wlo, C4, CC);
        gemm3<true, false, true, false>(fhi, flo, whi, wlo, bb2, x,
                                        x, nullptr, nullptr, BT, CC, C4);
    }

    // final LN (fp16) + fp16 head: logits = h @ wte^T
    ln_hf_kernel<<<BT, 256>>>(x, lnf_g, lnf_b, ahf);
    conv_hf_kernel<<<(unsigned)(((size_t)VV * CC + 255) / 256), 256>>>(
        wte, tef, (size_t)VV * CC);
    {
        dim3 grid((VV + 127) / 128, BT / 128);
        gemmh_kernel<<<grid, 256, GSMEMH>>>(ahf, tef, logits, BT, VV, CC);
    }
}

// round 5
// speedup vs baseline: 5.1122x; 2.3812x over previous
#include <cuda_runtime.h>
#include <cuda_bf16.h>
#include <cuda_fp16.h>
#include <math.h>
#include <stdint.h>

// ---------------- problem constants ----------------
#define NL   12
#define BB   4
#define TT   1024
#define CC   768
#define HH   12
#define HS   64
#define VV   50257
#define BT   (BB * TT)
#define C3   (3 * CC)
#define C4   (4 * CC)
#define SCALE 0.125f

// ---------------- device scratch ----------------
__device__ float g_x[BT * CC];
__device__ float g_qkv[BT * C3];
__device__ __nv_bfloat16 g_ahi[BT * CC];
__device__ __nv_bfloat16 g_alo[BT * CC];
__device__ __nv_bfloat16 g_fhi[BT * C4];
__device__ __nv_bfloat16 g_flo[BT * C4];
__device__ __nv_bfloat16 g_whi[C4 * CC];
__device__ __nv_bfloat16 g_wlo[C4 * CC];
__device__ __half g_ahf[BT * CC];
__device__ __half g_tef[(size_t)VV * CC];

// ---------------- PTX helpers ----------------
__device__ __forceinline__ uint32_t smem_u32(const void* p) {
    uint32_t a;
    asm("{ .reg .u64 t; cvta.to.shared.u64 t, %1; cvt.u32.u64 %0, t; }" : "=r"(a) : "l"(p));
    return a;
}
__device__ __forceinline__ void cp16(uint32_t dst, const void* src, int sz) {
    asm volatile("cp.async.ca.shared.global [%0], [%1], 16, %2;"
                 :: "r"(dst), "l"(src), "r"(sz) : "memory");
}
__device__ __forceinline__ void cp_commit() {
    asm volatile("cp.async.commit_group;" ::: "memory");
}
__device__ __forceinline__ void ldsm4(uint32_t* r, uint32_t a) {
    asm volatile("ldmatrix.sync.aligned.m8n8.x4.shared.b16 {%0,%1,%2,%3}, [%4];"
                 : "=r"(r[0]), "=r"(r[1]), "=r"(r[2]), "=r"(r[3]) : "r"(a));
}
__device__ __forceinline__ void mma_bf16(float* d, const uint32_t* a,
                                         uint32_t b0, uint32_t b1) {
    asm volatile(
        "mma.sync.aligned.m16n8k16.row.col.f32.bf16.bf16.f32 "
        "{%0,%1,%2,%3}, {%4,%5,%6,%7}, {%8,%9}, {%0,%1,%2,%3};"
        : "+f"(d[0]), "+f"(d[1]), "+f"(d[2]), "+f"(d[3])
        : "r"(a[0]), "r"(a[1]), "r"(a[2]), "r"(a[3]), "r"(b0), "r"(b1));
}
__device__ __forceinline__ void mma_fp16(float* d, const uint32_t* a,
                                         uint32_t b0, uint32_t b1) {
    asm volatile(
        "mma.sync.aligned.m16n8k16.row.col.f32.f16.f16.f32 "
        "{%0,%1,%2,%3}, {%4,%5,%6,%7}, {%8,%9}, {%0,%1,%2,%3};"
        : "+f"(d[0]), "+f"(d[1]), "+f"(d[2]), "+f"(d[3])
        : "r"(a[0]), "r"(a[1]), "r"(a[2]), "r"(a[3]), "r"(b0), "r"(b1));
}
__device__ __forceinline__ uint32_t packbf(float a, float b) {
    __nv_bfloat162 t = __floats2bfloat162_rn(a, b);
    return *reinterpret_cast<uint32_t*>(&t);
}
__device__ __forceinline__ float bfhi(float v) {
    return __bfloat162float(__float2bfloat16(v));
}

// ---------------- embedding ----------------
__global__ void embed_kernel(const int* __restrict__ inp,
                             const float* __restrict__ wte,
                             const float* __restrict__ wpe,
                             float* __restrict__ x) {
    int i = blockIdx.x * blockDim.x + threadIdx.x;
    if (i >= BT * CC) return;
    int c = i % CC;
    int bt = i / CC;
    int t = bt % TT;
    int tok = inp[bt];
    x[i] = wte[(size_t)tok * CC + c] + wpe[(size_t)t * CC + c];
}

// ---------------- layernorm -> bf16 hi/lo ----------------
__global__ void ln_hl_kernel(const float* __restrict__ in,
                             const float* __restrict__ g,
                             const float* __restrict__ b,
                             __nv_bfloat16* __restrict__ hi,
                             __nv_bfloat16* __restrict__ lo) {
    __shared__ float red[256];
    int row = blockIdx.x;
    int tid = threadIdx.x;
    const float* r = in + (size_t)row * CC;

    float s = 0.f;
    for (int c = tid; c < CC; c += 256) s += r[c];
    red[tid] = s; __syncthreads();
    for (int o = 128; o > 0; o >>= 1) { if (tid < o) red[tid] += red[tid + o]; __syncthreads(); }
    float mu = red[0] / CC;
    __syncthreads();

    float sq = 0.f;
    for (int c = tid; c < CC; c += 256) { float d = r[c] - mu; sq += d * d; }
    red[tid] = sq; __syncthreads();
    for (int o = 128; o > 0; o >>= 1) { if (tid < o) red[tid] += red[tid + o]; __syncthreads(); }
    float rstd = rsqrtf(red[0] / CC + 1e-5f);
    __syncthreads();

    size_t base = (size_t)row * CC;
    for (int c = tid; c < CC; c += 256) {
        float v = (r[c] - mu) * rstd * g[c] + b[c];
        __nv_bfloat16 h = __float2bfloat16(v);
        hi[base + c] = h;
        lo[base + c] = __float2bfloat16(v - __bfloat162float(h));
    }
}

// ---------------- final layernorm -> fp16 ----------------
__global__ void ln_hf_kernel(const float* __restrict__ in,
                             const float* __restrict__ g,
                             const float* __restrict__ b,
                             __half* __restrict__ out) {
    __shared__ float red[256];
    int row = blockIdx.x;
    int tid = threadIdx.x;
    const float* r = in + (size_t)row * CC;

    float s = 0.f;
    for (int c = tid; c < CC; c += 256) s += r[c];
    red[tid] = s; __syncthreads();
    for (int o = 128; o > 0; o >>= 1) { if (tid < o) red[tid] += red[tid + o]; __syncthreads(); }
    float mu = red[0] / CC;
    __syncthreads();

    float sq = 0.f;
    for (int c = tid; c < CC; c += 256) { float d = r[c] - mu; sq += d * d; }
    red[tid] = sq; __syncthreads();
    for (int o = 128; o > 0; o >>= 1) { if (tid < o) red[tid] += red[tid + o]; __syncthreads(); }
    float rstd = rsqrtf(red[0] / CC + 1e-5f);
    __syncthreads();

    size_t base = (size_t)row * CC;
    for (int c = tid; c < CC; c += 256)
        out[base + c] = __float2half((r[c] - mu) * rstd * g[c] + b[c]);
}

// ---------------- flash attention (bf16x3 mma, online softmax) ----------------
// One block = (b,h) x 64 q-rows. 4 warps, each warp 16 q-rows.
#define FA_STRIDE 144
#define FA_TILE   (64 * FA_STRIDE)       // 9216 B
#define FA_SMEM   (6 * FA_TILE)          // Qhi,Qlo,Khi,Klo,Vthi,Vtlo

__global__ void __launch_bounds__(128, 3)
fattn_kernel(const float* __restrict__ qkv,
             __nv_bfloat16* __restrict__ ohi,
             __nv_bfloat16* __restrict__ olo) {
    extern __shared__ char fs[];
    uint32_t sb = smem_u32(fs);
    int qt = 15 - blockIdx.x;            // heavy tiles first
    int bh = blockIdx.y;
    int h = bh % HH, b = bh / HH;
    int tid = threadIdx.x, lane = tid & 31, w = tid >> 5;
    int q0 = qt * 64;
    const float* base = qkv + (size_t)b * TT * C3 + (size_t)h * 3 * HS;

    // ---- load Q tile (rows q0..q0+63, 64 dims) as bf16 hi/lo ----
    {
        int r = tid >> 1, c0 = (tid & 1) * 32;
        const float* src = base + (size_t)(q0 + r) * C3 + c0;
        char* dh = fs + 0 * FA_TILE + r * FA_STRIDE + c0 * 2;
        char* dl = fs + 1 * FA_TILE + r * FA_STRIDE + c0 * 2;
        #pragma unroll
        for (int i = 0; i < 32; i += 4) {
            float4 v = *(const float4*)(src + i);
            float hx = bfhi(v.x), hy = bfhi(v.y), hz = bfhi(v.z), hw = bfhi(v.w);
            *(uint32_t*)(dh + i * 2)     = packbf(v.x, v.y);
            *(uint32_t*)(dh + i * 2 + 4) = packbf(v.z, v.w);
            *(uint32_t*)(dl + i * 2)     = packbf(v.x - hx, v.y - hy);
            *(uint32_t*)(dl + i * 2 + 4) = packbf(v.z - hz, v.w - hw);
        }
    }
    __syncthreads();

    // ---- preload Q A-fragments ----
    int lr = lane & 15, lh = (lane >> 4) * 16;
    uint32_t qh[4][4], ql[4][4];
    #pragma unroll
    for (int kk = 0; kk < 4; kk++) {
        uint32_t ad = sb + 0 * FA_TILE + (uint32_t)(w * 16 + lr) * FA_STRIDE + kk * 32 + lh;
        ldsm4(qh[kk], ad);
        ldsm4(ql[kk], ad + FA_TILE);
    }

    int g = lane >> 2, tg = lane & 3;
    int r0 = q0 + w * 16 + g;            // global row for c0,c1 (c2,c3 -> r0+8)
    float m0 = -1e30f, m1 = -1e30f, l0 = 0.f, l1 = 0.f;
    float O[8][4];
    #pragma unroll
    for (int f = 0; f < 8; f++)
        #pragma unroll
        for (int e = 0; e < 4; e++) O[f][e] = 0.f;

    for (int kt = 0; kt <= qt; kt++) {
        __syncthreads();    // previous iteration's smem reads done
        // ---- load K tile (row-major) + V tile (transposed) as bf16 hi/lo ----
        {
            int r = tid >> 1, c0 = (tid & 1) * 32;
            const float* ks = base + (size_t)(kt * 64 + r) * C3 + HS + c0;
            const float* vs = base + (size_t)(kt * 64 + r) * C3 + 2 * HS + c0;
            char* kh = fs + 2 * FA_TILE + r * FA_STRIDE + c0 * 2;
            char* kl = fs + 3 * FA_TILE + r * FA_STRIDE + c0 * 2;
            #pragma unroll
            for (int i = 0; i < 32; i += 4) {
                float4 v = *(const float4*)(ks + i);
                float hx = bfhi(v.x), hy = bfhi(v.y), hz = bfhi(v.z), hw = bfhi(v.w);
                *(uint32_t*)(kh + i * 2)     = packbf(v.x, v.y);
                *(uint32_t*)(kh + i * 2 + 4) = packbf(v.z, v.w);
                *(uint32_t*)(kl + i * 2)     = packbf(v.x - hx, v.y - hy);
                *(uint32_t*)(kl + i * 2 + 4) = packbf(v.z - hz, v.w - hw);
            }
            #pragma unroll
            for (int i = 0; i < 32; i++) {
                float v = vs[i];
                float hv = bfhi(v);
                int d = c0 + i;
                *(__nv_bfloat16*)(fs + 4 * FA_TILE + d * FA_STRIDE + r * 2) = __float2bfloat16(v);
                *(__nv_bfloat16*)(fs + 5 * FA_TILE + d * FA_STRIDE + r * 2) = __float2bfloat16(v - hv);
            }
        }
        __syncthreads();

        // ---- S = Q K^T (bf16x3) ----
        float S[8][4];
        #pragma unroll
        for (int f = 0; f < 8; f++)
            #pragma unroll
            for (int e = 0; e < 4; e++) S[f][e] = 0.f;

        #pragma unroll
        for (int kk = 0; kk < 4; kk++) {
            #pragma unroll
            for (int nt = 0; nt < 4; nt++) {
                uint32_t bd = sb + 2 * FA_TILE + (uint32_t)(nt * 16 + lr) * FA_STRIDE + kk * 32 + lh;
                uint32_t bhf[4], blf[4];
                ldsm4(bhf, bd);
                ldsm4(blf, bd + FA_TILE);
                #pragma unroll
                for (int sub = 0; sub < 2; sub++) {
                    float* d = S[nt * 2 + sub];
                    mma_bf16(d, qh[kk], bhf[sub], bhf[sub + 2]);
                    mma_bf16(d, qh[kk], blf[sub], blf[sub + 2]);
                    mma_bf16(d, ql[kk], bhf[sub], bhf[sub + 2]);
                }
            }
        }

        // ---- scale + causal mask ----
        #pragma unroll
        for (int f = 0; f < 8; f++)
            #pragma unroll
            for (int e = 0; e < 4; e++) S[f][e] *= SCALE;
        if (kt == qt) {
            #pragma unroll
            for (int f = 0; f < 8; f++) {
                int colb = kt * 64 + f * 8 + tg * 2;
                if (colb     > r0)     S[f][0] = -1e30f;
                if (colb + 1 > r0)     S[f][1] = -1e30f;
                if (colb     > r0 + 8) S[f][2] = -1e30f;
                if (colb + 1 > r0 + 8) S[f][3] = -1e30f;
            }
        }

        // ---- online softmax ----
        float mx0 = -1e30f, mx1 = -1e30f;
        #pragma unroll
        for (int f = 0; f < 8; f++) {
            mx0 = fmaxf(mx0, fmaxf(S[f][0], S[f][1]));
            mx1 = fmaxf(mx1, fmaxf(S[f][2], S[f][3]));
        }
        mx0 = fmaxf(mx0, __shfl_xor_sync(0xffffffffu, mx0, 1));
        mx0 = fmaxf(mx0, __shfl_xor_sync(0xffffffffu, mx0, 2));
        mx1 = fmaxf(mx1, __shfl_xor_sync(0xffffffffu, mx1, 1));
        mx1 = fmaxf(mx1, __shfl_xor_sync(0xffffffffu, mx1, 2));

        float mn0 = fmaxf(m0, mx0), mn1 = fmaxf(m1, mx1);
        float sc0 = __expf(m0 - mn0), sc1 = __expf(m1 - mn1);
        m0 = mn0; m1 = mn1;
        l0 *= sc0; l1 *= sc1;
        #pragma unroll
        for (int f = 0; f < 8; f++) {
            O[f][0] *= sc0; O[f][1] *= sc0;
            O[f][2] *= sc1; O[f][3] *= sc1;
        }

        float ps0 = 0.f, ps1 = 0.f;
        #pragma unroll
        for (int f = 0; f < 8; f++) {
            S[f][0] = __expf(S[f][0] - m0);
            S[f][1] = __expf(S[f][1] - m0);
            S[f][2] = __expf(S[f][2] - m1);
            S[f][3] = __expf(S[f][3] - m1);
            ps0 += S[f][0] + S[f][1];
            ps1 += S[f][2] + S[f][3];
        }
        ps0 += __shfl_xor_sync(0xffffffffu, ps0, 1);
        ps0 += __shfl_xor_sync(0xffffffffu, ps0, 2);
        ps1 += __shfl_xor_sync(0xffffffffu, ps1, 1);
        ps1 += __shfl_xor_sync(0xffffffffu, ps1, 2);
        l0 += ps0; l1 += ps1;

        // ---- build P fragments (hi/lo) from S accumulators ----
        uint32_t ph[4][4], pl[4][4];
        #pragma unroll
        for (int kk = 0; kk < 4; kk++) {
            float* A0 = S[2 * kk];
            float* A1 = S[2 * kk + 1];
            ph[kk][0] = packbf(A0[0], A0[1]);
            ph[kk][1] = packbf(A0[2], A0[3]);
            ph[kk][2] = packbf(A1[0], A1[1]);
            ph[kk][3] = packbf(A1[2], A1[3]);
            pl[kk][0] = packbf(A0[0] - bfhi(A0[0]), A0[1] - bfhi(A0[1]));
            pl[kk][1] = packbf(A0[2] - bfhi(A0[2]), A0[3] - bfhi(A0[3]));
            pl[kk][2] = packbf(A1[0] - bfhi(A1[0]), A1[1] - bfhi(A1[1]));
            pl[kk][3] = packbf(A1[2] - bfhi(A1[2]), A1[3] - bfhi(A1[3]));
        }

        // ---- O += P V (bf16x3) ----
        #pragma unroll
        for (int kk = 0; kk < 4; kk++) {
            #pragma unroll
            for (int nt = 0; nt < 4; nt++) {
                uint32_t bd = sb + 4 * FA_TILE + (uint32_t)(nt * 16 + lr) * FA_STRIDE + kk * 32 + lh;
                uint32_t bhf[4], blf[4];
                ldsm4(bhf, bd);
                ldsm4(blf, bd + FA_TILE);
                #pragma unroll
                for (int sub = 0; sub < 2; sub++) {
                    float* d = O[nt * 2 + sub];
                    mma_bf16(d, ph[kk], bhf[sub], bhf[sub + 2]);
                    mma_bf16(d, ph[kk], blf[sub], blf[sub + 2]);
                    mma_bf16(d, pl[kk], bhf[sub], bhf[sub + 2]);
                }
            }
        }
    }

    // ---- epilogue: O/l -> bf16 hi/lo, scattered store ----
    float inv0 = 1.f / l0, inv1 = 1.f / l1;
    #pragma unroll
    for (int f = 0; f < 8; f++) {
        int col = h * HS + f * 8 + tg * 2;
        size_t i0 = ((size_t)(b * TT + r0)) * CC + col;
        size_t i1 = i0 + (size_t)8 * CC;
        float v00 = O[f][0] * inv0, v01 = O[f][1] * inv0;
        float v10 = O[f][2] * inv1, v11 = O[f][3] * inv1;
        __nv_bfloat16 h00 = __float2bfloat16(v00);
        __nv_bfloat16 h01 = __float2bfloat16(v01);
        __nv_bfloat16 h10 = __float2bfloat16(v10);
        __nv_bfloat16 h11 = __float2bfloat16(v11);
        ohi[i0]     = h00; olo[i0]     = __float2bfloat16(v00 - __bfloat162float(h00));
        ohi[i0 + 1] = h01; olo[i0 + 1] = __float2bfloat16(v01 - __bfloat162float(h01));
        ohi[i1]     = h10; olo[i1]     = __float2bfloat16(v10 - __bfloat162float(h10));
        ohi[i1 + 1] = h11; olo[i1 + 1] = __float2bfloat16(v11 - __bfloat162float(h11));
    }
}

// ---------------- weight transpose + hi/lo split ----------------
__global__ void conv_wt_kernel(const float* __restrict__ W,
                               __nv_bfloat16* __restrict__ hi,
                               __nv_bfloat16* __restrict__ lo,
                               int K, int N) {
    __shared__ float ts[32][33];
    int k0 = blockIdx.y * 32, n0 = blockIdx.x * 32;
    int tx = threadIdx.x, ty = threadIdx.y;
    #pragma unroll
    for (int i = 0; i < 32; i += 8)
        ts[ty + i][tx] = W[(size_t)(k0 + ty + i) * N + n0 + tx];
    __syncthreads();
    #pragma unroll
    for (int i = 0; i < 32; i += 8) {
        float v = ts[tx][ty + i];
        size_t o = (size_t)(n0 + ty + i) * K + k0 + tx;
        __nv_bfloat16 h = __float2bfloat16(v);
        hi[o] = h;
        lo[o] = __float2bfloat16(v - __bfloat162float(h));
    }
}

// ---------------- wte -> fp16 ----------------
__global__ void conv_hf_kernel(const float* __restrict__ x,
                               __half* __restrict__ out, size_t n) {
    size_t i = (size_t)blockIdx.x * blockDim.x + threadIdx.x;
    if (i < n) out[i] = __float2half(x[i]);
}

// ---------------- HMMA bf16x3 GEMM (internal layers) ----------------
#define TSTRIDE  80
#define T_A_HI   0
#define T_A_LO   10240
#define T_B_HI   20480
#define T_B_LO   30720
#define T_STAGE  40960
#define GSMEM    (2 * T_STAGE)

template<bool BIAS, bool GELU, bool RES, bool OUTHL>
__global__ void __launch_bounds__(256, 2)
gemm3_kernel(const __nv_bfloat16* __restrict__ Ahi, const __nv_bfloat16* __restrict__ Alo,
             const __nv_bfloat16* __restrict__ Bhi, const __nv_bfloat16* __restrict__ Blo,
             const float* __restrict__ bias, const float* __restrict__ res,
             float* __restrict__ C,
             __nv_bfloat16* __restrict__ Chi, __nv_bfloat16* __restrict__ Clo,
             int M, int N, int K) {
    extern __shared__ char smem[];
    uint32_t sb = smem_u32(smem);
    int tid = threadIdx.x;
    int lane = tid & 31, wid = tid >> 5;
    int wr = wid >> 1, wc = wid & 1;
    int row0 = blockIdx.y * 128, col0 = blockIdx.x * 128;

    const char* pAhi = (const char*)Ahi;
    const char* pAlo = (const char*)Alo;
    const char* pBhi = (const char*)Bhi;
    const char* pBlo = (const char*)Blo;

    float acc[2][8][4];
    #pragma unroll
    for (int a = 0; a < 2; a++)
        #pragma unroll
        for (int b = 0; b < 8; b++)
            #pragma unroll
            for (int e = 0; e < 4; e++) acc[a][b][e] = 0.f;

    int nc = K / 32;
    size_t Kb = (size_t)K * 2;
    int l_row0 = tid >> 2;
    int l_p    = tid & 3;

    auto load_tile = [&](int c) {
        uint32_t s = sb + (uint32_t)(c & 1) * T_STAGE;
        size_t kb = (size_t)c * 64;
        #pragma unroll
        for (int i = 0; i < 2; i++) {
            int row = l_row0 + i * 64;
            uint32_t so = (uint32_t)row * TSTRIDE + (uint32_t)l_p * 16;
            size_t ao = (size_t)(row0 + row) * Kb + kb + (size_t)l_p * 16;
            cp16(s + T_A_HI + so, pAhi + ao, 16);
            cp16(s + T_A_LO + so, pAlo + ao, 16);
            int nr = col0 + row;
            int v = (nr < N) ? 16 : 0;
            size_t bo = (size_t)((nr < N) ? nr : 0) * Kb + kb + (size_t)l_p * 16;
            cp16(s + T_B_HI + so, pBhi + bo, v);
            cp16(s + T_B_LO + so, pBlo + bo, v);
        }
        cp_commit();
    };

    load_tile(0);

    int lr = lane & 15;
    int lh = (lane >> 4) * 16;

    for (int c = 0; c < nc; c++) {
        if (c + 1 < nc) {
            load_tile(c + 1);
            asm volatile("cp.async.wait_group 1;" ::: "memory");
        } else {
            asm volatile("cp.async.wait_group 0;" ::: "memory");
        }
        __syncthreads();

        uint32_t s = sb + (uint32_t)(c & 1) * T_STAGE;
        #pragma unroll
        for (int ks = 0; ks < 2; ks++) {
            uint32_t ko = ks * 32;
            uint32_t ah[2][4], al[2][4];
            #pragma unroll
            for (int mt = 0; mt < 2; mt++) {
                uint32_t ad = s + T_A_HI +
                              (uint32_t)(wr * 32 + mt * 16 + lr) * TSTRIDE + ko + lh;
                ldsm4(ah[mt], ad);
                ldsm4(al[mt], ad + (T_A_LO - T_A_HI));
            }
            #pragma unroll
            for (int nt = 0; nt < 4; nt++) {
                uint32_t bd = s + T_B_HI +
                              (uint32_t)(wc * 64 + nt * 16 + lr) * TSTRIDE + ko + lh;
                uint32_t bh[4], bl[4];
                ldsm4(bh, bd);
                ldsm4(bl, bd + (T_B_LO - T_B_HI));
                #pragma unroll
                for (int mt = 0; mt < 2; mt++) {
                    #pragma unroll
                    for (int sub = 0; sub < 2; sub++) {
                        float* d = acc[mt][nt * 2 + sub];
                        mma_bf16(d, ah[mt], bh[sub], bh[sub + 2]);
                        mma_bf16(d, ah[mt], bl[sub], bl[sub + 2]);
                        mma_bf16(d, al[mt], bh[sub], bh[sub + 2]);
                    }
                }
            }
        }
        __syncthreads();
    }

    int g = lane >> 2, tg = lane & 3;
    #pragma unroll
    for (int mt = 0; mt < 2; mt++) {
        int r0g = row0 + wr * 32 + mt * 16 + g;
        #pragma unroll
        for (int n8 = 0; n8 < 8; n8++) {
            int gc = col0 + wc * 64 + n8 * 8 + tg * 2;
            float* d = acc[mt][n8];
            #pragma unroll
            for (int e = 0; e < 4; e++) {
                int rr = r0g + ((e >= 2) ? 8 : 0);
                int cc_ = gc + (e & 1);
                if (cc_ < N) {
                    float v = d[e];
                    if (BIAS) v += bias[cc_];
                    if (GELU) v = 0.5f * v * (1.0f + erff(v * 0.7071067811865475f));
                    if (RES)  v += res[(size_t)rr * N + cc_];
                    size_t idx = (size_t)rr * N + cc_;
                    if (OUTHL) {
                        __nv_bfloat16 hv = __float2bfloat16(v);
                        Chi[idx] = hv;
                        Clo[idx] = __float2bfloat16(v - __bfloat162float(hv));
                    } else {
                        C[idx] = v;
                    }
                }
            }
        }
    }
}

// ---------------- HMMA fp16 GEMM (LM head) ----------------
#define H_A      0
#define H_B      10240
#define H_STAGE  20480
#define GSMEMH   (2 * H_STAGE)

__global__ void __launch_bounds__(256, 2)
gemmh_kernel(const __half* __restrict__ A, const __half* __restrict__ B,
             float* __restrict__ C, int M, int N, int K) {
    extern __shared__ char smem[];
    uint32_t sb = smem_u32(smem);
    int tid = threadIdx.x;
    int lane = tid & 31, wid = tid >> 5;
    int wr = wid >> 1, wc = wid & 1;
    int row0 = blockIdx.y * 128, col0 = blockIdx.x * 128;

    const char* pA = (const char*)A;
    const char* pB = (const char*)B;

    float acc[2][8][4];
    #pragma unroll
    for (int a = 0; a < 2; a++)
        #pragma unroll
        for (int b = 0; b < 8; b++)
            #pragma unroll
            for (int e = 0; e < 4; e++) acc[a][b][e] = 0.f;

    int nc = K / 32;
    size_t Kb = (size_t)K * 2;
    int l_row0 = tid >> 2;
    int l_p    = tid & 3;

    auto load_tile = [&](int c) {
        uint32_t s = sb + (uint32_t)(c & 1) * H_STAGE;
        size_t kb = (size_t)c * 64;
        #pragma unroll
        for (int i = 0; i < 2; i++) {
            int row = l_row0 + i * 64;
            uint32_t so = (uint32_t)row * TSTRIDE + (uint32_t)l_p * 16;
            size_t ao = (size_t)(row0 + row) * Kb + kb + (size_t)l_p * 16;
            cp16(s + H_A + so, pA + ao, 16);
            int nr = col0 + row;
            int v = (nr < N) ? 16 : 0;
            size_t bo = (size_t)((nr < N) ? nr : 0) * Kb + kb + (size_t)l_p * 16;
            cp16(s + H_B + so, pB + bo, v);
        }
        cp_commit();
    };

    load_tile(0);

    int lr = lane & 15;
    int lh = (lane >> 4) * 16;

    for (int c = 0; c < nc; c++) {
        if (c + 1 < nc) {
            load_tile(c + 1);
            asm volatile("cp.async.wait_group 1;" ::: "memory");
        } else {
            asm volatile("cp.async.wait_group 0;" ::: "memory");
        }
        __syncthreads();

        uint32_t s = sb + (uint32_t)(c & 1) * H_STAGE;
        #pragma unroll
        for (int ks = 0; ks < 2; ks++) {
            uint32_t ko = ks * 32;
            uint32_t ah[2][4];
            #pragma unroll
            for (int mt = 0; mt < 2; mt++) {
                uint32_t ad = s + H_A +
                              (uint32_t)(wr * 32 + mt * 16 + lr) * TSTRIDE + ko + lh;
                ldsm4(ah[mt], ad);
            }
            #pragma unroll
            for (int nt = 0; nt < 4; nt++) {
                uint32_t bd = s + H_B +
                              (uint32_t)(wc * 64 + nt * 16 + lr) * TSTRIDE + ko + lh;
                uint32_t bf[4];
                ldsm4(bf, bd);
                #pragma unroll
                for (int mt = 0; mt < 2; mt++) {
                    #pragma unroll
                    for (int sub = 0; sub < 2; sub++)
                        mma_fp16(acc[mt][nt * 2 + sub], ah[mt], bf[sub], bf[sub + 2]);
                }
            }
        }
        __syncthreads();
    }

    int g = lane >> 2, tg = lane & 3;
    #pragma unroll
    for (int mt = 0; mt < 2; mt++) {
        int r0g = row0 + wr * 32 + mt * 16 + g;
        #pragma unroll
        for (int n8 = 0; n8 < 8; n8++) {
            int gc = col0 + wc * 64 + n8 * 8 + tg * 2;
            float* d = acc[mt][n8];
            #pragma unroll
            for (int e = 0; e < 4; e++) {
                int rr = r0g + ((e >= 2) ? 8 : 0);
                int cc_ = gc + (e & 1);
                if (cc_ < N) C[(size_t)rr * N + cc_] = d[e];
            }
        }
    }
}

// ---------------- host orchestration ----------------
static void conv_wT(const float* W, __nv_bfloat16* hi, __nv_bfloat16* lo, int K, int N) {
    conv_wt_kernel<<<dim3(N / 32, K / 32), dim3(32, 8)>>>(W, hi, lo, K, N);
}

template<bool BIAS, bool GELU, bool RES, bool OUTHL>
static void gemm3(const __nv_bfloat16* ahi, const __nv_bfloat16* alo,
                  const __nv_bfloat16* bhi, const __nv_bfloat16* blo,
                  const float* bias, const float* res,
                  float* C, __nv_bfloat16* Chi, __nv_bfloat16* Clo,
                  int M, int N, int K) {
    dim3 grid((N + 127) / 128, M / 128);
    gemm3_kernel<BIAS, GELU, RES, OUTHL><<<grid, 256, GSMEM>>>(
        ahi, alo, bhi, blo, bias, res, C, Chi, Clo, M, N, K);
}

extern "C" void kernel_launch(void* const* d_in, const int* in_sizes, int n_in,
                              void* d_out, int out_size) {
    const int*   inp   = (const int*)  d_in[0];
    const float* wte   = (const float*)d_in[1];
    const float* wpe   = (const float*)d_in[2];
    const float* ln1_g = (const float*)d_in[3];
    const float* ln1_b = (const float*)d_in[4];
    const float* wqkv  = (const float*)d_in[5];
    const float* bqkv  = (const float*)d_in[6];
    const float* wout  = (const float*)d_in[7];
    const float* bout  = (const float*)d_in[8];
    const float* ln2_g = (const float*)d_in[9];
    const float* ln2_b = (const float*)d_in[10];
    const float* wfc1  = (const float*)d_in[11];
    const float* bfc1  = (const float*)d_in[12];
    const float* wfc2  = (const float*)d_in[13];
    const float* bfc2  = (const float*)d_in[14];
    const float* lnf_g = (const float*)d_in[15];
    const float* lnf_b = (const float*)d_in[16];
    float* logits = (float*)d_out;

    float *x, *qkv;
    __nv_bfloat16 *ahi, *alo, *fhi, *flo, *whi, *wlo;
    __half *ahf, *tef;
    cudaGetSymbolAddress((void**)&x,   g_x);
    cudaGetSymbolAddress((void**)&qkv, g_qkv);
    cudaGetSymbolAddress((void**)&ahi, g_ahi);
    cudaGetSymbolAddress((void**)&alo, g_alo);
    cudaGetSymbolAddress((void**)&fhi, g_fhi);
    cudaGetSymbolAddress((void**)&flo, g_flo);
    cudaGetSymbolAddress((void**)&whi, g_whi);
    cudaGetSymbolAddress((void**)&wlo, g_wlo);
    cudaGetSymbolAddress((void**)&ahf, g_ahf);
    cudaGetSymbolAddress((void**)&tef, g_tef);

    cudaFuncSetAttribute(gemm3_kernel<true,  false, false, false>, cudaFuncAttributeMaxDynamicSharedMemorySize, GSMEM);
    cudaFuncSetAttribute(gemm3_kernel<true,  false, true,  false>, cudaFuncAttributeMaxDynamicSharedMemorySize, GSMEM);
    cudaFuncSetAttribute(gemm3_kernel<true,  true,  false, true >, cudaFuncAttributeMaxDynamicSharedMemorySize, GSMEM);
    cudaFuncSetAttribute(gemmh_kernel, cudaFuncAttributeMaxDynamicSharedMemorySize, GSMEMH);
    cudaFuncSetAttribute(fattn_kernel, cudaFuncAttributeMaxDynamicSharedMemorySize, FA_SMEM);

    embed_kernel<<<(BT * CC + 255) / 256, 256>>>(inp, wte, wpe, x);

    for (int l = 0; l < NL; l++) {
        const float* g1  = ln1_g + (size_t)l * CC;
        const float* b1  = ln1_b + (size_t)l * CC;
        const float* wq  = wqkv  + (size_t)l * CC * C3;
        const float* bq  = bqkv  + (size_t)l * C3;
        const float* wo  = wout  + (size_t)l * CC * CC;
        const float* bo  = bout  + (size_t)l * CC;
        const float* g2  = ln2_g + (size_t)l * CC;
        const float* b2  = ln2_b + (size_t)l * CC;
        const float* w1  = wfc1  + (size_t)l * CC * C4;
        const float* bb1 = bfc1  + (size_t)l * C4;
        const float* w2  = wfc2  + (size_t)l * C4 * CC;
        const float* bb2 = bfc2  + (size_t)l * CC;

        ln_hl_kernel<<<BT, 256>>>(x, g1, b1, ahi, alo);
        conv_wT(wq, whi, wlo, CC, C3);
        gemm3<true, false, false, false>(ahi, alo, whi, wlo, bq, nullptr,
                                         qkv, nullptr, nullptr, BT, C3, CC);

        fattn_kernel<<<dim3(16, BB * HH), 128, FA_SMEM>>>(qkv, ahi, alo);

        conv_wT(wo, whi, wlo, CC, CC);
        gemm3<true, false, true, false>(ahi, alo, whi, wlo, bo, x,
                                        x, nullptr, nullptr, BT, CC, CC);

        ln_hl_kernel<<<BT, 256>>>(x, g2, b2, ahi, alo);
        conv_wT(w1, whi, wlo, CC, C4);
        gemm3<true, true, false, true>(ahi, alo, whi, wlo, bb1, nullptr,
                                       nullptr, fhi, flo, BT, C4, CC);

        conv_wT(w2, whi, wlo, C4, CC);
        gemm3<true, false, true, false>(fhi, flo, whi, wlo, bb2, x,
                                        x, nullptr, nullptr, BT, CC, C4);
    }

    ln_hf_kernel<<<BT, 256>>>(x, lnf_g, lnf_b, ahf);
    conv_hf_kernel<<<(unsigned)(((size_t)VV * CC + 255) / 256), 256>>>(
        wte, tef, (size_t)VV * CC);
    {
        dim3 grid((VV + 127) / 128, BT / 128);
        gemmh_kernel<<<grid, 256, GSMEMH>>>(ahf, tef, logits, BT, VV, CC);
    }
}